// round 16
// baseline (speedup 1.0000x reference)
#include <cuda_runtime.h>
#include <cuda_fp16.h>
#include <math.h>
#include <stdint.h>

// ============================================================================
// CrossAttention via fp16 mma.sync, 2-slice error compensation on Q/K/scores;
// single-slice fp16 on V / PV / proj. GEMM: 128x128 CTA tile, 4 warps of
// 64x64 (halves SMEM ldmatrix re-read traffic vs 8x(32x64)), 3-stage
// cp.async, one sync/iter. Q+K+V merged into one launch.
// ============================================================================

static const int Bb_ = 8, T_ = 1024, S_ = 1024, E_ = 768, Hh_ = 768;

#define STG_BYTES 16384           // 128 rows x 128B
#define NSTG 3
#define DSMEM_BYTES (NSTG * 2 * STG_BYTES)

// scratch
__device__ float g_scores[8 * 1024 * 1024];
__device__ __half g_xc[8192LL * 1536];      // x split; later attnout plain [*,768]
__device__ __half g_encc[8192LL * 1536];
__device__ __half g_qc[8192LL * 1536];
__device__ __half g_kc[8192LL * 1536];
__device__ __half g_vtc[8LL * 768 * 1024];  // plain fp16 v^T
__device__ __half g_attnc[8192LL * 1024];   // plain fp16 attn
__device__ __half g_wqt[768LL * 1536];
__device__ __half g_wkt[768LL * 1536];
__device__ __half g_wvt[768LL * 768];       // plain fp16
__device__ __half g_wpt[768LL * 768];       // plain fp16

// ---------------------------------------------------------------------------
static __device__ __forceinline__ uint32_t smem_u32(const void* p) {
    return (uint32_t)__cvta_generic_to_shared((void*)p);
}
static __device__ __forceinline__ void cp_async16(uint32_t dst, const void* src) {
    asm volatile("cp.async.cg.shared.global [%0], [%1], 16;" :: "r"(dst), "l"(src) : "memory");
}
#define CP_COMMIT() asm volatile("cp.async.commit_group;" ::: "memory")
#define CP_WAIT1()  asm volatile("cp.async.wait_group 1;" ::: "memory")

static __device__ __forceinline__ uint32_t swz128(uint32_t off) {
    return off ^ ((off >> 3) & 0x70);
}

#define LDSM_X4(r0, r1, r2, r3, addr) \
    asm volatile("ldmatrix.sync.aligned.m8n8.x4.shared.b16 {%0,%1,%2,%3}, [%4];" \
        : "=r"(r0), "=r"(r1), "=r"(r2), "=r"(r3) : "r"(addr))

static __device__ __forceinline__ void mma16816(
    float* d, const uint32_t* a, uint32_t b0, uint32_t b1)
{
    asm volatile(
        "mma.sync.aligned.m16n8k16.row.col.f32.f16.f16.f32 "
        "{%0,%1,%2,%3}, {%4,%5,%6,%7}, {%8,%9}, {%0,%1,%2,%3};"
        : "+f"(d[0]), "+f"(d[1]), "+f"(d[2]), "+f"(d[3])
        : "r"(a[0]), "r"(a[1]), "r"(a[2]), "r"(a[3]), "r"(b0), "r"(b1));
}

static __device__ __forceinline__ void split2(float x, float y, uint32_t& hh, uint32_t& ll) {
    __half hx = __float2half(x);
    __half hy = __float2half(y);
    __half lx = __float2half(x - __half2float(hx));
    __half ly = __float2half(y - __half2float(hy));
    hh = ((uint32_t)__half_as_ushort(hy) << 16) | __half_as_ushort(hx);
    ll = ((uint32_t)__half_as_ushort(ly) << 16) | __half_as_ushort(lx);
}
static __device__ __forceinline__ uint32_t pack2(float x, float y) {
    return ((uint32_t)__half_as_ushort(__float2half(y)) << 16)
         | __half_as_ushort(__float2half(x));
}

// ---------------------------------------------------------------------------
// NT GEMM: out = alpha * A @ B^T (+ bias). 128 threads, 4 warps of 64x64.
// A: [M,*] fp16 row stride lda; B: [N,*] row stride ldb. K2 % 64 == 0.
// mode 0: fp32 C [M,N]. mode 1: fp16 D [M,2N] (hi,lo). mode 2: (hi,hi).
// mode 3: fp16 D [M,N] plain. bias_row: bias indexed by output row.
// multi==2: z==1 -> {A2,B2,bias2,D2,mode2}; z==2 -> hardcoded V problem.
// ---------------------------------------------------------------------------
__global__ __launch_bounds__(128, 2)
void gemm_mma_nt(const __half* __restrict__ A,
                 const __half* __restrict__ B,
                 const float* __restrict__ bias,
                 float* __restrict__ C,
                 __half* __restrict__ D,
                 int mode, int bias_row, int multi,
                 const __half* __restrict__ A2,
                 const __half* __restrict__ B2,
                 const float* __restrict__ bias2,
                 __half* __restrict__ D2,
                 const __half* __restrict__ A3,
                 const __half* __restrict__ B3,
                 const float* __restrict__ bias3,
                 __half* __restrict__ D3,
                 int M, int N, int K2, float alpha,
                 long long sA, long long sB, long long sOut)
{
    extern __shared__ char dsmem_raw[];
    const uint32_t base = smem_u32(dsmem_raw);

    const int tid  = threadIdx.x;
    const int wid  = tid >> 5;
    const int lane = tid & 31;
    const int wm = wid & 1;          // warp row (64 rows)
    const int wn = wid >> 1;         // warp col (64 cols)

    long long z = blockIdx.z;
    int lda = K2, ldb = K2;
    int row0, col0;
    if (multi && z == 2) {
        // V problem (hardcoded): vt[b] = wvt @ enc_hi[b]^T, single-slice
        A = A3; B = B3; bias = bias3; D = D3;
        mode = 3; bias_row = 1;
        N = 1024; K2 = 768; lda = 768; ldb = 1536;
        sA = 0; sB = 1024LL * 1536; sOut = 768LL * 1024;
        const int t = blockIdx.y * 6 + blockIdx.x;     // 0..383
        z = t / 48;
        const int r = t - (int)z * 48;
        row0 = (r >> 3) * 128;
        col0 = (r & 7) * 128;
    } else {
        if (multi && z == 1) { A = A2; B = B2; bias = bias2; D = D2; mode = 2; }
        if (multi) z = 0;
        row0 = blockIdx.y * 128;
        col0 = blockIdx.x * 128;
    }

    const __half* Ab = A + z * sA + (long long)row0 * lda;
    const __half* Bb = B + z * sB + (long long)col0 * ldb;

    const int KI = K2 >> 6;

    // ldmatrix lane geometry
    const int g = lane >> 3;
    const int arow0 = wm * 64 + (g & 1) * 8 + (lane & 7);
    const int ach   = g >> 1;
    const int brow0 = wn * 64 + (g >> 1) * 8 + (lane & 7);
    const int bch   = g & 1;
    const int a7 = arow0 & 7;
    const int b7 = brow0 & 7;
    uint32_t arb[4], brb[4];
#pragma unroll
    for (int t = 0; t < 4; ++t) arb[t] = (uint32_t)(arow0 + t * 16) * 128u;
#pragma unroll
    for (int p = 0; p < 4; ++p) brb[p] = (uint32_t)(brow0 + p * 16) * 128u;

    float acc[4][8][4];
#pragma unroll
    for (int t = 0; t < 4; ++t)
#pragma unroll
        for (int u = 0; u < 8; ++u)
#pragma unroll
            for (int r = 0; r < 4; ++r) acc[t][u][r] = 0.0f;

    // loader: 1 row/thread, 8 x 16B chunks per operand
    const int r7 = tid & 7;
    const uint32_t rb = (uint32_t)tid * 128u;
    auto load_stage = [&](int kb) {
        const uint32_t sa = base + (kb % NSTG) * STG_BYTES;
        const uint32_t sb = base + NSTG * STG_BYTES + (kb % NSTG) * STG_BYTES;
        const long long k0 = (long long)kb * 64;
        const __half* ap = Ab + (long long)tid * lda + k0;
        const __half* bp = Bb + (long long)tid * ldb + k0;
#pragma unroll
        for (int c = 0; c < 8; ++c) {
            const uint32_t so = rb + (uint32_t)((c ^ r7) * 16);
            cp_async16(sa + so, ap + c * 8);
            cp_async16(sb + so, bp + c * 8);
        }
    };

    load_stage(0); CP_COMMIT();
    load_stage(1); CP_COMMIT();

    for (int it = 0; it < KI; ++it) {
        CP_WAIT1();
        __syncthreads();

        if (it + 2 < KI) load_stage(it + 2);
        CP_COMMIT();

        const int s = it % NSTG;
        const uint32_t sa = base + s * STG_BYTES;
        const uint32_t sb = base + NSTG * STG_BYTES + s * STG_BYTES;

#pragma unroll
        for (int kk = 0; kk < 4; ++kk) {
            uint32_t af[4][4];
            uint32_t bf[4][4];
            const uint32_t xa = (uint32_t)(((kk * 2 + ach) ^ a7) * 16);
            const uint32_t xb = (uint32_t)(((kk * 2 + bch) ^ b7) * 16);
#pragma unroll
            for (int t = 0; t < 4; ++t)
                LDSM_X4(af[t][0], af[t][1], af[t][2], af[t][3], sa + arb[t] + xa);
#pragma unroll
            for (int p = 0; p < 4; ++p)
                LDSM_X4(bf[p][0], bf[p][1], bf[p][2], bf[p][3], sb + brb[p] + xb);
#pragma unroll
            for (int t = 0; t < 4; ++t)
#pragma unroll
                for (int u = 0; u < 8; ++u)
                    mma16816(acc[t][u], af[t],
                             bf[u >> 1][(u & 1) * 2],
                             bf[u >> 1][(u & 1) * 2 + 1]);
        }
    }

    // ---- epilogue ----
    if (mode == 0) {
        float* Cz = C + z * sOut;
#pragma unroll
        for (int t = 0; t < 4; ++t) {
            const int r_lo = row0 + wm * 64 + t * 16 + (lane >> 2);
#pragma unroll
            for (int u = 0; u < 8; ++u) {
                const int c = col0 + wn * 64 + u * 8 + 2 * (lane & 3);
                float b0 = 0.f, b1 = 0.f;
                if (bias && !bias_row) { b0 = bias[c]; b1 = bias[c + 1]; }
                const float br0 = (bias && bias_row) ? bias[r_lo] : 0.f;
                const float br1 = (bias && bias_row) ? bias[r_lo + 8] : 0.f;
                float2 v0, v1;
                v0.x = acc[t][u][0] * alpha + b0 + br0;
                v0.y = acc[t][u][1] * alpha + b1 + br0;
                v1.x = acc[t][u][2] * alpha + b0 + br1;
                v1.y = acc[t][u][3] * alpha + b1 + br1;
                *(float2*)(Cz + (long long)r_lo * N + c) = v0;
                *(float2*)(Cz + (long long)(r_lo + 8) * N + c) = v1;
            }
        }
    } else if (mode == 3) {
        __half* Dz = D + z * sOut;
#pragma unroll
        for (int t = 0; t < 4; ++t) {
            const int r_lo = row0 + wm * 64 + t * 16 + (lane >> 2);
#pragma unroll
            for (int u = 0; u < 8; ++u) {
                const int c = col0 + wn * 64 + u * 8 + 2 * (lane & 3);
                float b0 = 0.f, b1 = 0.f;
                if (bias && !bias_row) { b0 = bias[c]; b1 = bias[c + 1]; }
#pragma unroll
                for (int hf = 0; hf < 2; ++hf) {
                    const int r = r_lo + hf * 8;
                    const float br = (bias && bias_row) ? bias[r] : 0.f;
                    const float vx = acc[t][u][hf * 2 + 0] * alpha + b0 + br;
                    const float vy = acc[t][u][hf * 2 + 1] * alpha + b1 + br;
                    *(uint32_t*)(Dz + (long long)r * N + c) = pack2(vx, vy);
                }
            }
        }
    } else {
        __half* Dz = D + z * sOut;
        const int N2 = 2 * N;
        const int m1 = (mode == 1);
#pragma unroll
        for (int t = 0; t < 4; ++t) {
            const int r_lo = row0 + wm * 64 + t * 16 + (lane >> 2);
#pragma unroll
            for (int u = 0; u < 8; ++u) {
                const int c = col0 + wn * 64 + u * 8 + 2 * (lane & 3);
                float b0 = 0.f, b1 = 0.f;
                if (bias && !bias_row) { b0 = bias[c]; b1 = bias[c + 1]; }
#pragma unroll
                for (int hf = 0; hf < 2; ++hf) {
                    const int r = r_lo + hf * 8;
                    const float br = (bias && bias_row) ? bias[r] : 0.f;
                    const float vx = acc[t][u][hf * 2 + 0] * alpha + b0 + br;
                    const float vy = acc[t][u][hf * 2 + 1] * alpha + b1 + br;
                    uint32_t hh, ll;
                    split2(vx, vy, hh, ll);
                    *(uint32_t*)(Dz + (long long)r * N2 + c)     = hh;
                    *(uint32_t*)(Dz + (long long)r * N2 + N + c) = m1 ? ll : hh;
                }
            }
        }
    }
}

// ---------------------------------------------------------------------------
// fp32 [R,K] -> fp16 [R,2K] split (hi,lo), 8 elems/thread. z picks src.
// ---------------------------------------------------------------------------
__global__ __launch_bounds__(256) void conv_split8_2(
    const float* __restrict__ src0, __half* __restrict__ dst0,
    const float* __restrict__ src1, __half* __restrict__ dst1,
    int K, long long total8)
{
    const long long i = (long long)blockIdx.x * 256 + threadIdx.x;
    if (i >= total8) return;
    const float* src = blockIdx.z ? src1 : src0;
    __half* dst = blockIdx.z ? dst1 : dst0;
    const int K8 = K >> 3;
    const long long row = i / K8;
    const int k0 = (int)(i - row * K8) << 3;

    const float4 va = *(const float4*)(src + row * K + k0);
    const float4 vb = *(const float4*)(src + row * K + k0 + 4);
    float f[8] = {va.x, va.y, va.z, va.w, vb.x, vb.y, vb.z, vb.w};
    uint32_t hh[4], ll[4];
#pragma unroll
    for (int j = 0; j < 4; ++j) split2(f[2 * j], f[2 * j + 1], hh[j], ll[j]);

    uint4 H = make_uint4(hh[0], hh[1], hh[2], hh[3]);
    uint4 L = make_uint4(ll[0], ll[1], ll[2], ll[3]);
    __half* d0 = dst + row * 2LL * K + k0;
    *(uint4*)(d0)     = H;
    *(uint4*)(d0 + K) = L;
}

// ---------------------------------------------------------------------------
// Weight transpose: fp32 [R,C] -> fp16. z<2: [C,2R] (hi,hi); z>=2: [C,R] plain.
// ---------------------------------------------------------------------------
__global__ __launch_bounds__(256) void convT_split_w(
    const float* __restrict__ s0, const float* __restrict__ s1,
    const float* __restrict__ s2, const float* __restrict__ s3,
    __half* __restrict__ d0, __half* __restrict__ d1,
    __half* __restrict__ d2, __half* __restrict__ d3,
    int R, int Csz)
{
    __shared__ float tile[32 * 33];
    const float* Sp = (blockIdx.z == 0) ? s0 : (blockIdx.z == 1) ? s1
                    : (blockIdx.z == 2) ? s2 : s3;
    __half* Dp = (blockIdx.z == 0) ? d0 : (blockIdx.z == 1) ? d1
               : (blockIdx.z == 2) ? d2 : d3;
    const int r0 = blockIdx.y * 32;
    const int c0 = blockIdx.x * 32;
    const int tid = threadIdx.x;
    const int tx = tid & 31;
    const int ty = tid >> 5;
#pragma unroll
    for (int j = 0; j < 4; ++j)
        tile[(ty + j * 8) * 33 + tx] = Sp[(long long)(r0 + ty + j * 8) * Csz + c0 + tx];
    __syncthreads();

    const int cl = tid >> 3;
    const int rs = (tid & 7) * 4;
    union { __half b[4]; unsigned long long u; } H;
#pragma unroll
    for (int j = 0; j < 4; ++j)
        H.b[j] = __float2half(tile[(rs + j) * 33 + cl]);
    if (blockIdx.z >= 2) {
        *(unsigned long long*)(Dp + (long long)(c0 + cl) * R + (r0 + rs)) = H.u;
    } else {
        const long long basee = (long long)(c0 + cl) * 2 * R + (r0 + rs);
        *(unsigned long long*)(Dp + basee)     = H.u;
        *(unsigned long long*)(Dp + basee + R) = H.u;
    }
}

// ---------------------------------------------------------------------------
// Fused softmax: fp32 row [1024] -> plain fp16 [1024].
// ---------------------------------------------------------------------------
__global__ __launch_bounds__(256) void softmax_h(
    const float* __restrict__ s, __half* __restrict__ dst)
{
    const long long row = blockIdx.x;
    const float* p = s + row * 1024;
    const int tid = threadIdx.x;

    float4 v = *(const float4*)(p + tid * 4);
    __shared__ float red[8];

    float m = fmaxf(fmaxf(v.x, v.y), fmaxf(v.z, v.w));
#pragma unroll
    for (int o = 16; o > 0; o >>= 1) m = fmaxf(m, __shfl_xor_sync(0xffffffffu, m, o));
    if ((tid & 31) == 0) red[tid >> 5] = m;
    __syncthreads();
    float bm = red[0];
#pragma unroll
    for (int i = 1; i < 8; ++i) bm = fmaxf(bm, red[i]);
    __syncthreads();

    v.x = __expf(v.x - bm); v.y = __expf(v.y - bm);
    v.z = __expf(v.z - bm); v.w = __expf(v.w - bm);
    float sum = v.x + v.y + v.z + v.w;
#pragma unroll
    for (int o = 16; o > 0; o >>= 1) sum += __shfl_xor_sync(0xffffffffu, sum, o);
    if ((tid & 31) == 0) red[tid >> 5] = sum;
    __syncthreads();
    float bs = red[0];
#pragma unroll
    for (int i = 1; i < 8; ++i) bs += red[i];

    const float inv = 1.0f / bs;
    uint2 H;
    H.x = pack2(v.x * inv, v.y * inv);
    H.y = pack2(v.z * inv, v.w * inv);
    *(uint2*)(dst + row * 1024 + tid * 4) = H;
}

// ---------------------------------------------------------------------------
extern "C" void kernel_launch(void* const* d_in, const int* in_sizes, int n_in,
                              void* d_out, int out_size)
{
    const float* x   = (const float*)d_in[0];
    const float* enc = (const float*)d_in[1];
    const float* Wq  = (const float*)d_in[2];
    const float* bq  = (const float*)d_in[3];
    const float* Wk  = (const float*)d_in[4];
    const float* bk  = (const float*)d_in[5];
    const float* Wv  = (const float*)d_in[6];
    const float* bv  = (const float*)d_in[7];
    const float* Wp  = (const float*)d_in[8];
    const float* bp  = (const float*)d_in[9];
    float* out = (float*)d_out;

    float* scores;
    __half *xc, *encc, *qc, *kc, *vtc, *attnc, *wqt, *wkt, *wvt, *wpt;
    cudaGetSymbolAddress((void**)&scores, g_scores);
    cudaGetSymbolAddress((void**)&xc, g_xc);
    cudaGetSymbolAddress((void**)&encc, g_encc);
    cudaGetSymbolAddress((void**)&qc, g_qc);
    cudaGetSymbolAddress((void**)&kc, g_kc);
    cudaGetSymbolAddress((void**)&vtc, g_vtc);
    cudaGetSymbolAddress((void**)&attnc, g_attnc);
    cudaGetSymbolAddress((void**)&wqt, g_wqt);
    cudaGetSymbolAddress((void**)&wkt, g_wkt);
    cudaGetSymbolAddress((void**)&wvt, g_wvt);
    cudaGetSymbolAddress((void**)&wpt, g_wpt);

    cudaFuncSetAttribute(gemm_mma_nt,
                         cudaFuncAttributeMaxDynamicSharedMemorySize, DSMEM_BYTES);

    const int BT = Bb_ * T_;                 // 8192
    const float scale = 1.0f / sqrtf((float)Hh_);
    dim3 blk256(256);
    dim3 blk128(128);

    // 1. Weight transposes (wq,wk dup hi; wv,wp plain), one launch
    {
        dim3 g(E_ / 32, E_ / 32, 4);
        convT_split_w<<<g, blk256>>>(Wq, Wk, Wv, Wp, wqt, wkt, wvt, wpt, E_, Hh_);
    }

    // 2. x & enc splits (hi,lo), one launch
    {
        long long t8 = (long long)BT * E_ / 8;
        dim3 g((unsigned)((t8 + 255) / 256), 1, 2);
        conv_split8_2<<<g, blk256>>>(x, xc, enc, encc, E_, t8);
    }

    // 3. Q + K + V^T in ONE launch: z=0 Q, z=1 K, z=2 V (hardcoded branch)
    {
        dim3 gqkv(Hh_ / 128, BT / 128, 3);   // (6, 64, 3) = 1152 CTAs
        gemm_mma_nt<<<gqkv, blk128, DSMEM_BYTES>>>(
            xc, wqt, bq, nullptr, qc, 1, 0, 2,
            encc, wkt, bk, kc,
            wvt, encc, bv, vtc,
            BT, Hh_, 2 * E_, 1.0f, 0, 0, 0);
    }

    // 4. scores[b] = q[b] k[b]^T * scale  (fp32)
    {
        dim3 g(S_ / 128, T_ / 128, Bb_);
        gemm_mma_nt<<<g, blk128, DSMEM_BYTES>>>(
            qc, kc, nullptr, scores, nullptr, 0, 0, 0,
            nullptr, nullptr, nullptr, nullptr,
            nullptr, nullptr, nullptr, nullptr,
            T_, S_, 2 * Hh_, scale,
            (long long)T_ * 2 * Hh_, (long long)S_ * 2 * Hh_,
            (long long)T_ * S_);
    }

    // 5. softmax -> plain fp16 attnc
    softmax_h<<<BT, blk256>>>(scores, attnc);

    // 6. attnout[b] = attn[b] @ v[b] -> plain fp16 xc [8192,768], K2=1024
    {
        dim3 g(Hh_ / 128, T_ / 128, Bb_);
        gemm_mma_nt<<<g, blk128, DSMEM_BYTES>>>(
            attnc, vtc, nullptr, nullptr, xc, 3, 0, 0,
            nullptr, nullptr, nullptr, nullptr,
            nullptr, nullptr, nullptr, nullptr,
            T_, Hh_, S_, 1.0f,
            (long long)T_ * S_, (long long)Hh_ * S_,
            (long long)T_ * Hh_);
    }

    // 7. out = attnout @ Wp + bp  (fp32), K2 = 768
    {
        dim3 g(E_ / 128, BT / 128, 1);
        gemm_mma_nt<<<g, blk128, DSMEM_BYTES>>>(
            xc, wpt, bp, out, nullptr, 0, 0, 0,
            nullptr, nullptr, nullptr, nullptr,
            nullptr, nullptr, nullptr, nullptr,
            BT, E_, Hh_, 1.0f, 0, 0, 0);
    }
}

// round 17
// speedup vs baseline: 2.0817x; 2.0817x over previous
#include <cuda_runtime.h>
#include <cuda_fp16.h>
#include <math.h>
#include <stdint.h>

// ============================================================================
// CrossAttention via fp16 mma.sync. Activations/weights feed projections as
// 2-slice (hi,lo)x(hi,hi) fp16 (22-bit effective); all projection OUTPUTS are
// plain fp16 (q,k,v,attn,attnout). Error budget measured across rounds:
// ~6.4e-4 total vs 1e-3 threshold. 8 warps of 32x64, 128x128 CTA tile, BK=64
// (SW128), 3-stage cp.async, one sync/iter, double-buffered ldmatrix frags.
// ============================================================================

static const int Bb_ = 8, T_ = 1024, S_ = 1024, E_ = 768, Hh_ = 768;

#define STG_BYTES 16384           // 128 rows x 128B
#define NSTG 3
#define DSMEM_BYTES (NSTG * 2 * STG_BYTES)

// scratch
__device__ float g_scores[8 * 1024 * 1024];
__device__ __half g_xc[8192LL * 1536];      // x split; later attnout plain [*,768]
__device__ __half g_encc[8192LL * 1536];
__device__ __half g_qc[8192LL * 768];       // plain fp16 q
__device__ __half g_kc[8192LL * 768];       // plain fp16 k
__device__ __half g_vtc[8LL * 768 * 1024];  // plain fp16 v^T
__device__ __half g_attnc[8192LL * 1024];   // plain fp16 attn
__device__ __half g_wqt[768LL * 1536];
__device__ __half g_wkt[768LL * 1536];
__device__ __half g_wvt[768LL * 768];       // plain fp16
__device__ __half g_wpt[768LL * 768];       // plain fp16

// ---------------------------------------------------------------------------
static __device__ __forceinline__ uint32_t smem_u32(const void* p) {
    return (uint32_t)__cvta_generic_to_shared((void*)p);
}
static __device__ __forceinline__ void cp_async16(uint32_t dst, const void* src) {
    asm volatile("cp.async.cg.shared.global [%0], [%1], 16;" :: "r"(dst), "l"(src) : "memory");
}
#define CP_COMMIT() asm volatile("cp.async.commit_group;" ::: "memory")
#define CP_WAIT1()  asm volatile("cp.async.wait_group 1;" ::: "memory")

static __device__ __forceinline__ uint32_t swz128(uint32_t off) {
    return off ^ ((off >> 3) & 0x70);
}

#define LDSM_X4(r0, r1, r2, r3, addr) \
    asm volatile("ldmatrix.sync.aligned.m8n8.x4.shared.b16 {%0,%1,%2,%3}, [%4];" \
        : "=r"(r0), "=r"(r1), "=r"(r2), "=r"(r3) : "r"(addr))

static __device__ __forceinline__ void mma16816(
    float* d, const uint32_t* a, uint32_t b0, uint32_t b1)
{
    asm volatile(
        "mma.sync.aligned.m16n8k16.row.col.f32.f16.f16.f32 "
        "{%0,%1,%2,%3}, {%4,%5,%6,%7}, {%8,%9}, {%0,%1,%2,%3};"
        : "+f"(d[0]), "+f"(d[1]), "+f"(d[2]), "+f"(d[3])
        : "r"(a[0]), "r"(a[1]), "r"(a[2]), "r"(a[3]), "r"(b0), "r"(b1));
}

static __device__ __forceinline__ void split2(float x, float y, uint32_t& hh, uint32_t& ll) {
    __half hx = __float2half(x);
    __half hy = __float2half(y);
    __half lx = __float2half(x - __half2float(hx));
    __half ly = __float2half(y - __half2float(hy));
    hh = ((uint32_t)__half_as_ushort(hy) << 16) | __half_as_ushort(hx);
    ll = ((uint32_t)__half_as_ushort(ly) << 16) | __half_as_ushort(lx);
}
static __device__ __forceinline__ uint32_t pack2(float x, float y) {
    return ((uint32_t)__half_as_ushort(__float2half(y)) << 16)
         | __half_as_ushort(__float2half(x));
}

// ---------------------------------------------------------------------------
// NT GEMM: out = alpha * A @ B^T (+ bias). 256 threads, 8 warps of 32x64.
// A: [M,*] fp16 row stride lda; B: [N,*] row stride ldb. K2 % 64 == 0.
// mode 0: fp32 C [M,N]. mode 3: fp16 D [M,N] plain.
// bias_row: bias indexed by output row.
// multi==2: blockIdx.z==1 -> swap {A2,B2,bias2,D2}; z==2 -> hardcoded V
//   problem (vt[b][768,1024] = A3[768,768] @ B3[b][1024, hi of 1536]^T).
// ---------------------------------------------------------------------------
__global__ __launch_bounds__(256, 2)
void gemm_mma_nt(const __half* __restrict__ A,
                 const __half* __restrict__ B,
                 const float* __restrict__ bias,
                 float* __restrict__ C,
                 __half* __restrict__ D,
                 int mode, int bias_row, int multi,
                 const __half* __restrict__ A2,
                 const __half* __restrict__ B2,
                 const float* __restrict__ bias2,
                 __half* __restrict__ D2,
                 const __half* __restrict__ A3,
                 const __half* __restrict__ B3,
                 const float* __restrict__ bias3,
                 __half* __restrict__ D3,
                 int M, int N, int K2, float alpha,
                 long long sA, long long sB, long long sOut)
{
    extern __shared__ char dsmem_raw[];
    const uint32_t base = smem_u32(dsmem_raw);

    const int tid  = threadIdx.x;
    const int wid  = tid >> 5;
    const int lane = tid & 31;
    const int wm = wid & 3;
    const int wn = wid >> 2;

    long long z = blockIdx.z;
    int lda = K2, ldb = K2;
    int row0, col0;
    if (multi && z == 2) {
        // V problem (hardcoded): vt[b] = wvt @ enc_hi[b]^T, single-slice
        A = A3; B = B3; bias = bias3; D = D3;
        mode = 3; bias_row = 1;
        N = 1024; K2 = 768; lda = 768; ldb = 1536;
        sA = 0; sB = 1024LL * 1536; sOut = 768LL * 1024;
        const int t = blockIdx.y * 6 + blockIdx.x;     // 0..383
        z = t / 48;
        const int r = t - (int)z * 48;
        row0 = (r >> 3) * 128;
        col0 = (r & 7) * 128;
    } else {
        if (multi && z == 1) { A = A2; B = B2; bias = bias2; D = D2; }
        if (multi) z = 0;
        row0 = blockIdx.y * 128;
        col0 = blockIdx.x * 128;
    }

    const __half* Ab = A + z * sA + (long long)row0 * lda;
    const __half* Bb = B + z * sB + (long long)col0 * ldb;

    const int KI = K2 >> 6;

    const int g = lane >> 3;
    const int arow = wm * 32 + (g & 1) * 8 + (lane & 7);
    const int ach  = g >> 1;
    const int brow = wn * 64 + (g >> 1) * 8 + (lane & 7);
    const int bch  = g & 1;
    const int a7 = arow & 7;
    const int b7 = brow & 7;
    uint32_t arb[2], brb[4];
#pragma unroll
    for (int t = 0; t < 2; ++t) arb[t] = (uint32_t)(arow + t * 16) * 128u;
#pragma unroll
    for (int p = 0; p < 4; ++p) brb[p] = (uint32_t)(brow + p * 16) * 128u;

    float acc[2][8][4];
#pragma unroll
    for (int t = 0; t < 2; ++t)
#pragma unroll
        for (int u = 0; u < 8; ++u)
#pragma unroll
            for (int r = 0; r < 4; ++r) acc[t][u][r] = 0.0f;

    // loader: 4 rows/thread x 1 chunk of 16B per operand
    const int ldr0 = tid >> 3;
    const int ldc  = tid & 7;
    auto load_stage = [&](int kb) {
        const uint32_t sa = base + (kb % NSTG) * STG_BYTES;
        const uint32_t sb = base + NSTG * STG_BYTES + (kb % NSTG) * STG_BYTES;
        const long long k0 = (long long)kb * 64 + ldc * 8;
#pragma unroll
        for (int i = 0; i < 4; ++i) {
            const int r = ldr0 + i * 32;
            const uint32_t so = swz128((uint32_t)(r * 128 + ldc * 16));
            cp_async16(sa + so, Ab + (long long)r * lda + k0);
            cp_async16(sb + so, Bb + (long long)r * ldb + k0);
        }
    };

    load_stage(0); CP_COMMIT();
    load_stage(1); CP_COMMIT();

    uint32_t af[2][2][4];    // [buf][t][frag]
    uint32_t bf[2][4][4];    // [buf][p][frag]

    for (int it = 0; it < KI; ++it) {
        CP_WAIT1();
        __syncthreads();

        if (it + 2 < KI) load_stage(it + 2);
        CP_COMMIT();

        const int s = it % NSTG;
        const uint32_t sa = base + s * STG_BYTES;
        const uint32_t sb = base + NSTG * STG_BYTES + s * STG_BYTES;

        // preload kk = 0 fragments
        {
            const uint32_t xa = (uint32_t)((ach ^ a7) * 16);
            const uint32_t xb = (uint32_t)((bch ^ b7) * 16);
#pragma unroll
            for (int t = 0; t < 2; ++t)
                LDSM_X4(af[0][t][0], af[0][t][1], af[0][t][2], af[0][t][3],
                        sa + arb[t] + xa);
#pragma unroll
            for (int p = 0; p < 4; ++p)
                LDSM_X4(bf[0][p][0], bf[0][p][1], bf[0][p][2], bf[0][p][3],
                        sb + brb[p] + xb);
        }

#pragma unroll
        for (int kk = 0; kk < 4; ++kk) {
            const int cur = kk & 1;
            const int nxt = cur ^ 1;
            if (kk < 3) {
                const uint32_t xa = (uint32_t)((((kk + 1) * 2 + ach) ^ a7) * 16);
                const uint32_t xb = (uint32_t)((((kk + 1) * 2 + bch) ^ b7) * 16);
#pragma unroll
                for (int t = 0; t < 2; ++t)
                    LDSM_X4(af[nxt][t][0], af[nxt][t][1], af[nxt][t][2], af[nxt][t][3],
                            sa + arb[t] + xa);
#pragma unroll
                for (int p = 0; p < 4; ++p)
                    LDSM_X4(bf[nxt][p][0], bf[nxt][p][1], bf[nxt][p][2], bf[nxt][p][3],
                            sb + brb[p] + xb);
            }
#pragma unroll
            for (int t = 0; t < 2; ++t)
#pragma unroll
                for (int u = 0; u < 8; ++u)
                    mma16816(acc[t][u], af[cur][t],
                             bf[cur][u >> 1][(u & 1) * 2],
                             bf[cur][u >> 1][(u & 1) * 2 + 1]);
        }
    }

    // ---- epilogue ----
    if (mode == 0) {
        float* Cz = C + z * sOut;
#pragma unroll
        for (int t = 0; t < 2; ++t) {
            const int r_lo = row0 + wm * 32 + t * 16 + (lane >> 2);
#pragma unroll
            for (int u = 0; u < 8; ++u) {
                const int c = col0 + wn * 64 + u * 8 + 2 * (lane & 3);
                float b0 = 0.f, b1 = 0.f;
                if (bias && !bias_row) { b0 = bias[c]; b1 = bias[c + 1]; }
                const float br0 = (bias && bias_row) ? bias[r_lo] : 0.f;
                const float br1 = (bias && bias_row) ? bias[r_lo + 8] : 0.f;
                float2 v0, v1;
                v0.x = acc[t][u][0] * alpha + b0 + br0;
                v0.y = acc[t][u][1] * alpha + b1 + br0;
                v1.x = acc[t][u][2] * alpha + b0 + br1;
                v1.y = acc[t][u][3] * alpha + b1 + br1;
                *(float2*)(Cz + (long long)r_lo * N + c) = v0;
                *(float2*)(Cz + (long long)(r_lo + 8) * N + c) = v1;
            }
        }
    } else {
        __half* Dz = D + z * sOut;
#pragma unroll
        for (int t = 0; t < 2; ++t) {
            const int r_lo = row0 + wm * 32 + t * 16 + (lane >> 2);
#pragma unroll
            for (int u = 0; u < 8; ++u) {
                const int c = col0 + wn * 64 + u * 8 + 2 * (lane & 3);
                float b0 = 0.f, b1 = 0.f;
                if (bias && !bias_row) { b0 = bias[c]; b1 = bias[c + 1]; }
#pragma unroll
                for (int hf = 0; hf < 2; ++hf) {
                    const int r = r_lo + hf * 8;
                    const float br = (bias && bias_row) ? bias[r] : 0.f;
                    const float vx = acc[t][u][hf * 2 + 0] * alpha + b0 + br;
                    const float vy = acc[t][u][hf * 2 + 1] * alpha + b1 + br;
                    *(uint32_t*)(Dz + (long long)r * N + c) = pack2(vx, vy);
                }
            }
        }
    }
}

// ---------------------------------------------------------------------------
// fp32 [R,K] -> fp16 [R,2K] split (hi,lo), 8 elems/thread. z picks src.
// ---------------------------------------------------------------------------
__global__ __launch_bounds__(256) void conv_split8_2(
    const float* __restrict__ src0, __half* __restrict__ dst0,
    const float* __restrict__ src1, __half* __restrict__ dst1,
    int K, long long total8)
{
    const long long i = (long long)blockIdx.x * 256 + threadIdx.x;
    if (i >= total8) return;
    const float* src = blockIdx.z ? src1 : src0;
    __half* dst = blockIdx.z ? dst1 : dst0;
    const int K8 = K >> 3;
    const long long row = i / K8;
    const int k0 = (int)(i - row * K8) << 3;

    const float4 va = *(const float4*)(src + row * K + k0);
    const float4 vb = *(const float4*)(src + row * K + k0 + 4);
    float f[8] = {va.x, va.y, va.z, va.w, vb.x, vb.y, vb.z, vb.w};
    uint32_t hh[4], ll[4];
#pragma unroll
    for (int j = 0; j < 4; ++j) split2(f[2 * j], f[2 * j + 1], hh[j], ll[j]);

    uint4 H = make_uint4(hh[0], hh[1], hh[2], hh[3]);
    uint4 L = make_uint4(ll[0], ll[1], ll[2], ll[3]);
    __half* d0 = dst + row * 2LL * K + k0;
    *(uint4*)(d0)     = H;
    *(uint4*)(d0 + K) = L;
}

// ---------------------------------------------------------------------------
// Weight transpose: fp32 [R,C] -> fp16. z<2: [C,2R] (hi,hi); z>=2: [C,R] plain.
// ---------------------------------------------------------------------------
__global__ __launch_bounds__(256) void convT_split_w(
    const float* __restrict__ s0, const float* __restrict__ s1,
    const float* __restrict__ s2, const float* __restrict__ s3,
    __half* __restrict__ d0, __half* __restrict__ d1,
    __half* __restrict__ d2, __half* __restrict__ d3,
    int R, int Csz)
{
    __shared__ float tile[32 * 33];
    const float* Sp = (blockIdx.z == 0) ? s0 : (blockIdx.z == 1) ? s1
                    : (blockIdx.z == 2) ? s2 : s3;
    __half* Dp = (blockIdx.z == 0) ? d0 : (blockIdx.z == 1) ? d1
               : (blockIdx.z == 2) ? d2 : d3;
    const int r0 = blockIdx.y * 32;
    const int c0 = blockIdx.x * 32;
    const int tid = threadIdx.x;
    const int tx = tid & 31;
    const int ty = tid >> 5;
#pragma unroll
    for (int j = 0; j < 4; ++j)
        tile[(ty + j * 8) * 33 + tx] = Sp[(long long)(r0 + ty + j * 8) * Csz + c0 + tx];
    __syncthreads();

    const int cl = tid >> 3;
    const int rs = (tid & 7) * 4;
    union { __half b[4]; unsigned long long u; } H;
#pragma unroll
    for (int j = 0; j < 4; ++j)
        H.b[j] = __float2half(tile[(rs + j) * 33 + cl]);
    if (blockIdx.z >= 2) {
        *(unsigned long long*)(Dp + (long long)(c0 + cl) * R + (r0 + rs)) = H.u;
    } else {
        const long long basee = (long long)(c0 + cl) * 2 * R + (r0 + rs);
        *(unsigned long long*)(Dp + basee)     = H.u;
        *(unsigned long long*)(Dp + basee + R) = H.u;
    }
}

// ---------------------------------------------------------------------------
// Fused softmax: fp32 row [1024] -> plain fp16 [1024].
// ---------------------------------------------------------------------------
__global__ __launch_bounds__(256) void softmax_h(
    const float* __restrict__ s, __half* __restrict__ dst)
{
    const long long row = blockIdx.x;
    const float* p = s + row * 1024;
    const int tid = threadIdx.x;

    float4 v = *(const float4*)(p + tid * 4);
    __shared__ float red[8];

    float m = fmaxf(fmaxf(v.x, v.y), fmaxf(v.z, v.w));
#pragma unroll
    for (int o = 16; o > 0; o >>= 1) m = fmaxf(m, __shfl_xor_sync(0xffffffffu, m, o));
    if ((tid & 31) == 0) red[tid >> 5] = m;
    __syncthreads();
    float bm = red[0];
#pragma unroll
    for (int i = 1; i < 8; ++i) bm = fmaxf(bm, red[i]);
    __syncthreads();

    v.x = __expf(v.x - bm); v.y = __expf(v.y - bm);
    v.z = __expf(v.z - bm); v.w = __expf(v.w - bm);
    float sum = v.x + v.y + v.z + v.w;
#pragma unroll
    for (int o = 16; o > 0; o >>= 1) sum += __shfl_xor_sync(0xffffffffu, sum, o);
    if ((tid & 31) == 0) red[tid >> 5] = sum;
    __syncthreads();
    float bs = red[0];
#pragma unroll
    for (int i = 1; i < 8; ++i) bs += red[i];

    const float inv = 1.0f / bs;
    uint2 H;
    H.x = pack2(v.x * inv, v.y * inv);
    H.y = pack2(v.z * inv, v.w * inv);
    *(uint2*)(dst + row * 1024 + tid * 4) = H;
}

// ---------------------------------------------------------------------------
extern "C" void kernel_launch(void* const* d_in, const int* in_sizes, int n_in,
                              void* d_out, int out_size)
{
    const float* x   = (const float*)d_in[0];
    const float* enc = (const float*)d_in[1];
    const float* Wq  = (const float*)d_in[2];
    const float* bq  = (const float*)d_in[3];
    const float* Wk  = (const float*)d_in[4];
    const float* bk  = (const float*)d_in[5];
    const float* Wv  = (const float*)d_in[6];
    const float* bv  = (const float*)d_in[7];
    const float* Wp  = (const float*)d_in[8];
    const float* bp  = (const float*)d_in[9];
    float* out = (float*)d_out;

    float* scores;
    __half *xc, *encc, *qc, *kc, *vtc, *attnc, *wqt, *wkt, *wvt, *wpt;
    cudaGetSymbolAddress((void**)&scores, g_scores);
    cudaGetSymbolAddress((void**)&xc, g_xc);
    cudaGetSymbolAddress((void**)&encc, g_encc);
    cudaGetSymbolAddress((void**)&qc, g_qc);
    cudaGetSymbolAddress((void**)&kc, g_kc);
    cudaGetSymbolAddress((void**)&vtc, g_vtc);
    cudaGetSymbolAddress((void**)&attnc, g_attnc);
    cudaGetSymbolAddress((void**)&wqt, g_wqt);
    cudaGetSymbolAddress((void**)&wkt, g_wkt);
    cudaGetSymbolAddress((void**)&wvt, g_wvt);
    cudaGetSymbolAddress((void**)&wpt, g_wpt);

    cudaFuncSetAttribute(gemm_mma_nt,
                         cudaFuncAttributeMaxDynamicSharedMemorySize, DSMEM_BYTES);

    const int BT = Bb_ * T_;                 // 8192
    const float scale = 1.0f / sqrtf((float)Hh_);
    dim3 blk(256);

    // 1. Weight transposes (wq,wk dup hi; wv,wp plain), one launch
    {
        dim3 g(E_ / 32, E_ / 32, 4);
        convT_split_w<<<g, blk>>>(Wq, Wk, Wv, Wp, wqt, wkt, wvt, wpt, E_, Hh_);
    }

    // 2. x & enc splits (hi,lo), one launch
    {
        long long t8 = (long long)BT * E_ / 8;
        dim3 g((unsigned)((t8 + 255) / 256), 1, 2);
        conv_split8_2<<<g, blk>>>(x, xc, enc, encc, E_, t8);
    }

    // 3. Q + K + V^T in ONE launch, all plain fp16 outputs (mode 3)
    {
        dim3 gqkv(Hh_ / 128, BT / 128, 3);   // (6, 64, 3) = 1152 CTAs
        gemm_mma_nt<<<gqkv, blk, DSMEM_BYTES>>>(
            xc, wqt, bq, nullptr, qc, 3, 0, 2,
            encc, wkt, bk, kc,
            wvt, encc, bv, vtc,
            BT, Hh_, 2 * E_, 1.0f, 0, 0, 0);
    }

    // 4. scores[b] = q[b] k[b]^T * scale  (fp32), K2 = 768 (plain q,k)
    {
        dim3 g(S_ / 128, T_ / 128, Bb_);
        gemm_mma_nt<<<g, blk, DSMEM_BYTES>>>(
            qc, kc, nullptr, scores, nullptr, 0, 0, 0,
            nullptr, nullptr, nullptr, nullptr,
            nullptr, nullptr, nullptr, nullptr,
            T_, S_, Hh_, scale,
            (long long)T_ * Hh_, (long long)S_ * Hh_,
            (long long)T_ * S_);
    }

    // 5. softmax -> plain fp16 attnc
    softmax_h<<<BT, blk>>>(scores, attnc);

    // 6. attnout[b] = attn[b] @ v[b] -> plain fp16 xc [8192,768], K2=1024
    {
        dim3 g(Hh_ / 128, T_ / 128, Bb_);
        gemm_mma_nt<<<g, blk, DSMEM_BYTES>>>(
            attnc, vtc, nullptr, nullptr, xc, 3, 0, 0,
            nullptr, nullptr, nullptr, nullptr,
            nullptr, nullptr, nullptr, nullptr,
            T_, Hh_, S_, 1.0f,
            (long long)T_ * S_, (long long)Hh_ * S_,
            (long long)T_ * Hh_);
    }

    // 7. out = attnout @ Wp + bp  (fp32), K2 = 768
    {
        dim3 g(E_ / 128, BT / 128, 1);
        gemm_mma_nt<<<g, blk, DSMEM_BYTES>>>(
            xc, wpt, bp, out, nullptr, 0, 0, 0,
            nullptr, nullptr, nullptr, nullptr,
            nullptr, nullptr, nullptr, nullptr,
            BT, E_, Hh_, 1.0f, 0, 0, 0);
    }
}